// round 6
// baseline (speedup 1.0000x reference)
#include <cuda_runtime.h>
#include <cuda_bf16.h>
#include <math.h>

#define NN 100000
#define EE 1600000

// ---------------- scratch ----------------
__device__ float g_h [NN * 128];
__device__ float g_xl[NN * 128];
__device__ float g_xr[NN * 128];
__device__ __nv_bfloat16 g_ah[NN * 128];      // A hi (hn)
__device__ __nv_bfloat16 g_al[NN * 128];      // A lo
__device__ __nv_bfloat16 g_wh[5 * 128 * 128]; // weights hi, transposed [n][k]
__device__ __nv_bfloat16 g_wl[5 * 128 * 128]; // weights lo
__device__ int g_cnt[NN];
__device__ int g_cur[NN];
__device__ int g_offs[NN + 1];
__device__ int g_esrc[EE + NN];

// bf16 split helpers
__device__ __forceinline__ void splitbf(float v, unsigned short& h, unsigned short& l) {
    __nv_bfloat16 hb = __float2bfloat16_rn(v);
    h = __bfloat16_as_ushort(hb);
    l = __bfloat16_as_ushort(__float2bfloat16_rn(v - __bfloat162float(hb)));
}

// ---------------- CSR build ----------------
__global__ void zero_cnt_kernel() {
    int i = blockIdx.x * blockDim.x + threadIdx.x;
    if (i < NN) g_cnt[i] = 0;
}
__global__ void hist_kernel(const int* __restrict__ ei) {
    int e = blockIdx.x * blockDim.x + threadIdx.x;
    if (e < EE) atomicAdd(&g_cnt[ei[EE + e]], 1);
}
// scan + self-loop placement (self-loop occupies last slot of each segment)
__global__ void scan_kernel() {
    __shared__ int sh[1024];
    const int CH = 98;
    int t = threadIdx.x;
    int start = t * CH;
    int s = 0;
    for (int j = 0; j < CH; j++) {
        int idx = start + j;
        if (idx < NN) s += g_cnt[idx] + 1;
    }
    sh[t] = s;
    __syncthreads();
    for (int off = 1; off < 1024; off <<= 1) {
        int u = (t >= off) ? sh[t - off] : 0;
        __syncthreads();
        sh[t] += u;
        __syncthreads();
    }
    int run = (t == 0) ? 0 : sh[t - 1];
    for (int j = 0; j < CH; j++) {
        int idx = start + j;
        if (idx >= NN) break;
        int v = g_cnt[idx] + 1;
        g_cur[idx] = run;
        run += v;
        g_offs[idx + 1] = run;
        g_esrc[run - 1] = idx;   // self-loop in last slot
    }
    if (t == 0) g_offs[0] = 0;
}
__global__ void scatter_kernel(const int* __restrict__ ei) {
    int e = blockIdx.x * blockDim.x + threadIdx.x;
    if (e < EE) {
        int s = ei[e];
        int d = ei[EE + e];
        int p = atomicAdd(&g_cur[d], 1);
        g_esrc[p] = s;
    }
}

// ---------------- weight convert: transpose + bf16 split ----------------
__global__ void convert_w_kernel(const float* __restrict__ Wp, const float* __restrict__ Wl,
                                 const float* __restrict__ Wr) {
    int i = blockIdx.x * blockDim.x + threadIdx.x;
    if (i >= 5 * 16384) return;
    int s = i >> 14, r = i & 16383;
    int n = r >> 7, k = r & 127;
    const float* src;
    if (s == 0) src = Wp;
    else if (s == 1) src = Wl;
    else if (s == 2) src = Wr;
    else if (s == 3) src = Wl + 16384;
    else src = Wr + 16384;
    float v = src[k * 128 + n];   // transpose -> [n][k]
    unsigned short h, l;
    splitbf(v, h, l);
    g_wh[i] = __ushort_as_bfloat16(h);
    g_wl[i] = __ushort_as_bfloat16(l);
}

// ---------------- LayerNorm (standalone, used once after proj): g_h -> g_ah/g_al --
__global__ void ln_kernel(const float* __restrict__ gamma, const float* __restrict__ beta) {
    int gw = (blockIdx.x * blockDim.x + threadIdx.x) >> 5;
    int lane = threadIdx.x & 31;
    if (gw >= NN) return;
    float4 h4 = ((const float4*)g_h)[(size_t)gw * 32 + lane];
    float s = h4.x + h4.y + h4.z + h4.w;
    float ss = h4.x * h4.x + h4.y * h4.y + h4.z * h4.z + h4.w * h4.w;
#pragma unroll
    for (int o = 16; o > 0; o >>= 1) {
        s  += __shfl_xor_sync(0xffffffffu, s, o);
        ss += __shfl_xor_sync(0xffffffffu, ss, o);
    }
    float mu = s * (1.f / 128.f);
    float var = ss * (1.f / 128.f) - mu * mu;
    float rs = rsqrtf(var + 1e-5f);
    float4 g4 = ((const float4*)gamma)[lane];
    float4 b4 = ((const float4*)beta)[lane];
    float o0 = (h4.x - mu) * rs * g4.x + b4.x;
    float o1 = (h4.y - mu) * rs * g4.y + b4.y;
    float o2 = (h4.z - mu) * rs * g4.z + b4.z;
    float o3 = (h4.w - mu) * rs * g4.w + b4.w;
    unsigned short h0, l0, h1, l1, h2, l2, h3, l3;
    splitbf(o0, h0, l0); splitbf(o1, h1, l1); splitbf(o2, h2, l2); splitbf(o3, h3, l3);
    uint2 hh, ll;
    hh.x = (unsigned)h0 | ((unsigned)h1 << 16);
    hh.y = (unsigned)h2 | ((unsigned)h3 << 16);
    ll.x = (unsigned)l0 | ((unsigned)l1 << 16);
    ll.y = (unsigned)l2 | ((unsigned)l3 << 16);
    ((uint2*)g_ah)[(size_t)gw * 32 + lane] = hh;
    ((uint2*)g_al)[(size_t)gw * 32 + lane] = ll;
}

// ---------------- mma.sync split-bf16 GEMM ----------------
// 256 threads = 8 warps in 2(M) x 4(N); warp tile 64x32; full K=128 in smem.
// If Aext != 0: stage A by splitting fp32 Aext inline (proj GEMM path).
// blockIdx.y selects (wslot, bias, C) pair for merged xl/xr launches.
#define SPAD 136
#define SMAT (128 * SPAD)

__device__ __forceinline__ void mma16816(float* c, unsigned a0, unsigned a1, unsigned a2,
                                         unsigned a3, unsigned b0, unsigned b1) {
    asm volatile(
        "mma.sync.aligned.m16n8k16.row.col.f32.bf16.bf16.f32 "
        "{%0,%1,%2,%3}, {%4,%5,%6,%7}, {%8,%9}, {%0,%1,%2,%3};"
        : "+f"(c[0]), "+f"(c[1]), "+f"(c[2]), "+f"(c[3])
        : "r"(a0), "r"(a1), "r"(a2), "r"(a3), "r"(b0), "r"(b1));
}

__global__ void __launch_bounds__(256, 1)
mma_gemm_kernel(const float* __restrict__ Aext,
                int wslot0, int wslot1,
                const float* __restrict__ bias0, const float* __restrict__ bias1,
                int csel0, int csel1) {
    extern __shared__ __nv_bfloat16 sm[];
    __nv_bfloat16* sAh = sm;
    __nv_bfloat16* sAl = sm + SMAT;
    __nv_bfloat16* sBh = sm + 2 * SMAT;
    __nv_bfloat16* sBl = sm + 3 * SMAT;

    int tid = threadIdx.x, wid = tid >> 5, lane = tid & 31;
    int m0 = blockIdx.x * 128;
    int which = blockIdx.y;
    int wslot = which ? wslot1 : wslot0;
    const float* bias = which ? bias1 : bias0;
    int csel = which ? csel1 : csel0;
    const __nv_bfloat16* Bh = g_wh + wslot * 16384;
    const __nv_bfloat16* Bl = g_wl + wslot * 16384;
    float* C = (csel == 0) ? g_h : ((csel == 1) ? g_xl : g_xr);

    // stage B (bf16 hi/lo from gmem)
    for (int i = tid; i < 2048; i += 256) {
        int row = i >> 4, c8 = i & 15;
        int so = row * SPAD + c8 * 8;
        *(uint4*)(sBh + so) = *(const uint4*)(Bh + row * 128 + c8 * 8);
        *(uint4*)(sBl + so) = *(const uint4*)(Bl + row * 128 + c8 * 8);
    }
    // stage A
    if (Aext) {
        // fp32 load + inline split
        for (int i = tid; i < 4096; i += 256) {
            int row = i >> 5, c4 = i & 31;
            int gr = m0 + row;
            float4 v = make_float4(0.f, 0.f, 0.f, 0.f);
            if (gr < NN) v = *(const float4*)(Aext + (size_t)gr * 128 + c4 * 4);
            unsigned short h0, l0, h1, l1, h2, l2, h3, l3;
            splitbf(v.x, h0, l0); splitbf(v.y, h1, l1);
            splitbf(v.z, h2, l2); splitbf(v.w, h3, l3);
            uint2 hh, ll;
            hh.x = (unsigned)h0 | ((unsigned)h1 << 16);
            hh.y = (unsigned)h2 | ((unsigned)h3 << 16);
            ll.x = (unsigned)l0 | ((unsigned)l1 << 16);
            ll.y = (unsigned)l2 | ((unsigned)l3 << 16);
            int so = row * SPAD + c4 * 4;
            *(uint2*)(sAh + so) = hh;
            *(uint2*)(sAl + so) = ll;
        }
    } else {
        const uint4 z4 = make_uint4(0, 0, 0, 0);
        for (int i = tid; i < 2048; i += 256) {
            int row = i >> 4, c8 = i & 15;
            int so = row * SPAD + c8 * 8;
            int gr = m0 + row;
            uint4 vh = z4, vl = z4;
            if (gr < NN) {
                vh = *(const uint4*)(g_ah + (size_t)gr * 128 + c8 * 8);
                vl = *(const uint4*)(g_al + (size_t)gr * 128 + c8 * 8);
            }
            *(uint4*)(sAh + so) = vh;
            *(uint4*)(sAl + so) = vl;
        }
    }
    __syncthreads();

    int wm = wid >> 2, wn = wid & 3;
    int g = lane >> 2, tg = lane & 3;

    float acc[4][4][4];
#pragma unroll
    for (int mf = 0; mf < 4; mf++)
#pragma unroll
        for (int nf = 0; nf < 4; nf++)
#pragma unroll
            for (int j = 0; j < 4; j++) acc[mf][nf][j] = 0.f;

    int arow = wm * 64 + g;
    int brow = wn * 32 + g;
    int kbase = tg * 2;

#pragma unroll 2
    for (int ks = 0; ks < 8; ks++) {
        int kk = ks * 16 + kbase;
        unsigned bh[4][2], bl[4][2];
#pragma unroll
        for (int nf = 0; nf < 4; nf++) {
            int ro = (brow + nf * 8) * SPAD + kk;
            bh[nf][0] = *(const unsigned*)(sBh + ro);
            bh[nf][1] = *(const unsigned*)(sBh + ro + 8);
            bl[nf][0] = *(const unsigned*)(sBl + ro);
            bl[nf][1] = *(const unsigned*)(sBl + ro + 8);
        }
#pragma unroll
        for (int mf = 0; mf < 4; mf++) {
            int ro = (arow + mf * 16) * SPAD + kk;
            unsigned ah0 = *(const unsigned*)(sAh + ro);
            unsigned ah1 = *(const unsigned*)(sAh + ro + 8 * SPAD);
            unsigned ah2 = *(const unsigned*)(sAh + ro + 8);
            unsigned ah3 = *(const unsigned*)(sAh + ro + 8 * SPAD + 8);
            unsigned al0 = *(const unsigned*)(sAl + ro);
            unsigned al1 = *(const unsigned*)(sAl + ro + 8 * SPAD);
            unsigned al2 = *(const unsigned*)(sAl + ro + 8);
            unsigned al3 = *(const unsigned*)(sAl + ro + 8 * SPAD + 8);
#pragma unroll
            for (int nf = 0; nf < 4; nf++) {
                mma16816(acc[mf][nf], ah0, ah1, ah2, ah3, bh[nf][0], bh[nf][1]);
                mma16816(acc[mf][nf], ah0, ah1, ah2, ah3, bl[nf][0], bl[nf][1]);
                mma16816(acc[mf][nf], al0, al1, al2, al3, bh[nf][0], bh[nf][1]);
            }
        }
    }

#pragma unroll
    for (int nf = 0; nf < 4; nf++) {
        int col = wn * 32 + nf * 8 + tg * 2;
        float b0 = bias[col], b1 = bias[col + 1];
#pragma unroll
        for (int mf = 0; mf < 4; mf++) {
            int r0 = m0 + wm * 64 + mf * 16 + g;
            if (r0 < NN) {
                float2 v0 = make_float2(acc[mf][nf][0] + b0, acc[mf][nf][1] + b1);
                *(float2*)(C + (size_t)r0 * 128 + col) = v0;
            }
            int r1 = r0 + 8;
            if (r1 < NN) {
                float2 v1 = make_float2(acc[mf][nf][2] + b0, acc[mf][nf][3] + b1);
                *(float2*)(C + (size_t)r1 * 128 + col) = v1;
            }
        }
    }
}

// ---------------- fused GATv2 attention + aggregation (warp per dst node) ------
// h_new = relu(agg + gb) + h_old ; optionally also LayerNorm(h_new) -> g_ah/g_al
__device__ __forceinline__ float head_logit(float4 xl, float4 xr, float4 at) {
    float m0 = xl.x + xr.x, m1 = xl.y + xr.y, m2 = xl.z + xr.z, m3 = xl.w + xr.w;
    float p = ((m0 > 0.f) ? m0 : 0.2f * m0) * at.x + ((m1 > 0.f) ? m1 : 0.2f * m1) * at.y
            + ((m2 > 0.f) ? m2 : 0.2f * m2) * at.z + ((m3 > 0.f) ? m3 : 0.2f * m3) * at.w;
    p += __shfl_xor_sync(0xffffffffu, p, 1);
    p += __shfl_xor_sync(0xffffffffu, p, 2);
    p += __shfl_xor_sync(0xffffffffu, p, 4);
    return p;
}

__global__ void edge_kernel(const float* __restrict__ att, const float* __restrict__ gb,
                            int do_ln, const float* __restrict__ gamma,
                            const float* __restrict__ beta) {
    int gw = (blockIdx.x * blockDim.x + threadIdx.x) >> 5;
    int lane = threadIdx.x & 31;
    if (gw >= NN) return;
    int off = g_offs[gw], end = g_offs[gw + 1];
    const float4* xl4 = (const float4*)g_xl;
    float4 xr = ((const float4*)g_xr)[(size_t)gw * 32 + lane];
    float4 at = ((const float4*)att)[lane];

    float m = -1e30f, ssum = 0.f;
    float4 acc = make_float4(0.f, 0.f, 0.f, 0.f);

    int e = off;
    int rem = (end - off) & 3;
    for (int r = 0; r < rem; r++, e++) {
        int s0 = g_esrc[e];
        float4 x0 = xl4[(size_t)s0 * 32 + lane];
        float p = head_logit(x0, xr, at);
        float nm = fmaxf(m, p);
        float corr = __expf(m - nm);
        float w = __expf(p - nm);
        ssum = ssum * corr + w;
        acc.x = acc.x * corr + w * x0.x;
        acc.y = acc.y * corr + w * x0.y;
        acc.z = acc.z * corr + w * x0.z;
        acc.w = acc.w * corr + w * x0.w;
        m = nm;
    }
    for (; e < end; e += 4) {
        int s0 = g_esrc[e], s1 = g_esrc[e + 1], s2 = g_esrc[e + 2], s3 = g_esrc[e + 3];
        float4 x0 = xl4[(size_t)s0 * 32 + lane];
        float4 x1 = xl4[(size_t)s1 * 32 + lane];
        float4 x2 = xl4[(size_t)s2 * 32 + lane];
        float4 x3 = xl4[(size_t)s3 * 32 + lane];
        float p0 = head_logit(x0, xr, at);
        float p1 = head_logit(x1, xr, at);
        float p2 = head_logit(x2, xr, at);
        float p3 = head_logit(x3, xr, at);
        float nm = fmaxf(fmaxf(m, fmaxf(p0, p1)), fmaxf(p2, p3));
        float corr = __expf(m - nm);
        float w0 = __expf(p0 - nm);
        float w1 = __expf(p1 - nm);
        float w2 = __expf(p2 - nm);
        float w3 = __expf(p3 - nm);
        ssum = ssum * corr + w0 + w1 + w2 + w3;
        acc.x = acc.x * corr + w0 * x0.x + w1 * x1.x + w2 * x2.x + w3 * x3.x;
        acc.y = acc.y * corr + w0 * x0.y + w1 * x1.y + w2 * x2.y + w3 * x3.y;
        acc.z = acc.z * corr + w0 * x0.z + w1 * x1.z + w2 * x2.z + w3 * x3.z;
        acc.w = acc.w * corr + w0 * x0.w + w1 * x1.w + w2 * x2.w + w3 * x3.w;
        m = nm;
    }
    float inv = 1.f / ssum;
    float4 gb4 = ((const float4*)gb)[lane];
    float4 id = ((const float4*)g_h)[(size_t)gw * 32 + lane];
    float4 o;
    o.x = fmaxf(acc.x * inv + gb4.x, 0.f) + id.x;
    o.y = fmaxf(acc.y * inv + gb4.y, 0.f) + id.y;
    o.z = fmaxf(acc.z * inv + gb4.z, 0.f) + id.z;
    o.w = fmaxf(acc.w * inv + gb4.w, 0.f) + id.w;
    ((float4*)g_h)[(size_t)gw * 32 + lane] = o;

    if (do_ln) {
        float s = o.x + o.y + o.z + o.w;
        float ss = o.x * o.x + o.y * o.y + o.z * o.z + o.w * o.w;
#pragma unroll
        for (int sh = 16; sh > 0; sh >>= 1) {
            s  += __shfl_xor_sync(0xffffffffu, s, sh);
            ss += __shfl_xor_sync(0xffffffffu, ss, sh);
        }
        float mu = s * (1.f / 128.f);
        float var = ss * (1.f / 128.f) - mu * mu;
        float rs = rsqrtf(var + 1e-5f);
        float4 g4 = ((const float4*)gamma)[lane];
        float4 b4 = ((const float4*)beta)[lane];
        float o0 = (o.x - mu) * rs * g4.x + b4.x;
        float o1 = (o.y - mu) * rs * g4.y + b4.y;
        float o2 = (o.z - mu) * rs * g4.z + b4.z;
        float o3 = (o.w - mu) * rs * g4.w + b4.w;
        unsigned short h0, l0, h1, l1, h2, l2, h3, l3;
        splitbf(o0, h0, l0); splitbf(o1, h1, l1); splitbf(o2, h2, l2); splitbf(o3, h3, l3);
        uint2 hh, ll;
        hh.x = (unsigned)h0 | ((unsigned)h1 << 16);
        hh.y = (unsigned)h2 | ((unsigned)h3 << 16);
        ll.x = (unsigned)l0 | ((unsigned)l1 << 16);
        ll.y = (unsigned)l2 | ((unsigned)l3 << 16);
        ((uint2*)g_ah)[(size_t)gw * 32 + lane] = hh;
        ((uint2*)g_al)[(size_t)gw * 32 + lane] = ll;
    }
}

// ---------------- fused classification + h copy (warp per row) ----------------
__global__ void class_copy_kernel(const float* __restrict__ Wc, const float* __restrict__ bc,
                                  float* __restrict__ out) {
    __shared__ float sWc[128 * 16];
    __shared__ float sbc[16];
    int t = threadIdx.x;
    for (int i = t; i < 2048; i += 256) sWc[i] = Wc[i];
    if (t < 16) sbc[t] = bc[t];
    __syncthreads();

    int gw = (blockIdx.x * blockDim.x + t) >> 5;
    int lane = t & 31;
    if (gw >= NN) return;
    float4 h4 = ((const float4*)g_h)[(size_t)gw * 32 + lane];
    // copy h to second output region (coalesced)
    ((float4*)(out + (size_t)NN * 16))[(size_t)gw * 32 + lane] = h4;

    float p[16];
    const float* w0 = sWc + (lane * 4 + 0) * 16;
    const float* w1 = sWc + (lane * 4 + 1) * 16;
    const float* w2 = sWc + (lane * 4 + 2) * 16;
    const float* w3 = sWc + (lane * 4 + 3) * 16;
#pragma unroll
    for (int j = 0; j < 16; j++)
        p[j] = h4.x * w0[j] + h4.y * w1[j] + h4.z * w2[j] + h4.w * w3[j];
#pragma unroll
    for (int sh = 16; sh > 0; sh >>= 1)
#pragma unroll
        for (int j = 0; j < 16; j++)
            p[j] += __shfl_xor_sync(0xffffffffu, p[j], sh);
    if (lane < 16) out[(size_t)gw * 16 + lane] = p[lane] + sbc[lane];
}

// ---------------- launcher ----------------
extern "C" void kernel_launch(void* const* d_in, const int* in_sizes, int n_in,
                              void* d_out, int out_size) {
    const float* x    = (const float*)d_in[0];
    const int*   ei   = (const int*)  d_in[1];
    const float* Wp   = (const float*)d_in[2];
    const float* bp   = (const float*)d_in[3];
    const float* ln_g = (const float*)d_in[4];
    const float* ln_b = (const float*)d_in[5];
    const float* Wl   = (const float*)d_in[6];
    const float* bl   = (const float*)d_in[7];
    const float* Wr   = (const float*)d_in[8];
    const float* br   = (const float*)d_in[9];
    const float* att  = (const float*)d_in[10];
    const float* gb   = (const float*)d_in[11];
    const float* Wc   = (const float*)d_in[12];
    const float* bc   = (const float*)d_in[13];
    float* out = (float*)d_out;

    const int SMEM_BYTES = 4 * SMAT * 2;
    cudaFuncSetAttribute(mma_gemm_kernel, cudaFuncAttributeMaxDynamicSharedMemorySize, SMEM_BYTES);

    // CSR by destination
    zero_cnt_kernel<<<(NN + 255) / 256, 256>>>();
    hist_kernel<<<EE / 256, 256>>>(ei);
    scan_kernel<<<1, 1024>>>();
    scatter_kernel<<<EE / 256, 256>>>(ei);

    // weight conversion
    convert_w_kernel<<<(5 * 16384 + 255) / 256, 256>>>(Wp, Wl, Wr);

    const int GG = (NN + 127) / 128;
    // h = x @ Wp + bp  (fp32 A split inline)
    mma_gemm_kernel<<<dim3(GG, 1), 256, SMEM_BYTES>>>(x, 0, 0, bp, bp, 0, 0);

    // LN after proj
    ln_kernel<<<(NN * 32 + 255) / 256, 256>>>(ln_g, ln_b);

    // layer 0: xl/xr GEMMs merged, edge fused with next LN
    mma_gemm_kernel<<<dim3(GG, 2), 256, SMEM_BYTES>>>(nullptr, 1, 2, bl, br, 1, 2);
    edge_kernel<<<(NN * 32 + 255) / 256, 256>>>(att, gb, 1, ln_g + 128, ln_b + 128);

    // layer 1
    mma_gemm_kernel<<<dim3(GG, 2), 256, SMEM_BYTES>>>(nullptr, 3, 4, bl + 128, br + 128, 1, 2);
    edge_kernel<<<(NN * 32 + 255) / 256, 256>>>(att + 128, gb + 128, 0, nullptr, nullptr);

    // classification + h copy
    class_copy_kernel<<<(NN * 32 + 255) / 256, 256>>>(Wc, bc, out);
}